// round 14
// baseline (speedup 1.0000x reference)
#include <cuda_runtime.h>
#include <cuda_bf16.h>
#include <math.h>

// Shapes fixed by the problem: B=16384, D=64, H=1024, CLAMP=10.
#define B_ROWS 16384
#define D_DIM  64
#define H_DIM  1024
#define CLAMPV 10.0f
#define NTHREADS 128   // 4 warps = 4 rows per block; 4 blocks/SM

typedef unsigned long long ull;

// Packed weights, per step i (3072 floats each):
//   [0,1024)    : W1m column i   (masked, m0-sorted)
//   [1024,2048) : W2m row i      (mu row, masked)
//   [2048,3072) : W2m row 64+i   (alpha row, masked)
__device__ __align__(16) float g_w[64 * 3072];
__device__ __align__(16) float g_b1p[H_DIM];
// Per-step chunk-activity masks (8 chunks of 128 units):
//   bits [0:8)  W1 chunk nonzero   (c*128+128 > S_i)
//   bits [8:12) mu chunk nonzero   (c*128 < Pmu_i), c<4 (Pmu <= 512 always)
//   bits [12:20) alpha chunk nonzero (c*128 < Pal_i)
//   bits [20:28) tanh-refresh chunk  (overlaps [S_i, E2_i), i<63)
__device__ unsigned g_masks[64];

// m0[h] = h % 63 (values 0..62), H sorted stably by m0.
__host__ __device__ __forceinline__ int start_ge(int v) {
    return (v <= 16) ? 17 * v : 16 * v + 16;
}

__device__ __forceinline__ float tanh_mufu(float x) {
    float y; asm("tanh.approx.f32 %0, %1;" : "=f"(y) : "f"(x)); return y;
}
__device__ __forceinline__ ull ffma2(ull a, ull b, ull c) {
    ull d;
    asm("fma.rn.f32x2 %0, %1, %2, %3;" : "=l"(d) : "l"(a), "l"(b), "l"(c));
    return d;
}
__device__ __forceinline__ ull mk2(float lo, float hi) {
    ull r; asm("mov.b64 %0, {%1, %2};" : "=l"(r) : "f"(lo), "f"(hi)); return r;
}
__device__ __forceinline__ void un2(ull u, float& lo, float& hi) {
    asm("mov.b64 {%0, %1}, %2;" : "=f"(lo), "=f"(hi) : "l"(u));
}
__device__ __forceinline__ void lds2(ull& a, ull& b, unsigned addr) {
    asm volatile("ld.shared.v2.u64 {%0, %1}, [%2];" : "=l"(a), "=l"(b) : "r"(addr));
}
__device__ __forceinline__ void cp16(unsigned smem_dst, const void* gsrc) {
    asm volatile("cp.async.cg.shared.global [%0], [%1], 16;" :: "r"(smem_dst), "l"(gsrc));
}
__device__ __forceinline__ void cp_commit() {
    asm volatile("cp.async.commit_group;" ::: "memory");
}
__device__ __forceinline__ void cp_wait1() {
    asm volatile("cp.async.wait_group 1;" ::: "memory");
}

// ---------------- prep: permute + mask + pack weights + masks ----------------
__global__ void maf_prep(const float* __restrict__ W1,
                         const float* __restrict__ b1,
                         const float* __restrict__ W2) {
    int gid = blockIdx.x * blockDim.x + threadIdx.x;
    if (gid >= 64 * 3072) return;
    int i   = gid / 3072;
    int rem = gid - i * 3072;
    int sec = rem >> 10;
    int p   = rem & 1023;
    int v, k2;
    if (p < 272) { v = p / 17; k2 = p - v * 17; }
    else         { int r = p - 272; v = 16 + (r >> 4); k2 = r & 15; }
    int h = v + 63 * k2;

    float val;
    if (sec == 0)      val = (i <= v)            ? W1[h * 64 + i]          : 0.0f;
    else if (sec == 1) val = (v < (i >> 1))      ? W2[i * 1024 + h]        : 0.0f;
    else               val = (v < 32 + (i >> 1)) ? W2[(64 + i) * 1024 + h] : 0.0f;
    g_w[gid] = val;

    if (gid < 1024) {
        int pp = gid;
        int vv, kk;
        if (pp < 272) { vv = pp / 17; kk = pp - vv * 17; }
        else          { int r = pp - 272; vv = 16 + (r >> 4); kk = r & 15; }
        g_b1p[gid] = b1[vv + 63 * kk];
    }

    if (gid < 64) {
        int st = gid;
        int S   = start_ge(st);
        int Pmu = start_ge(st >> 1);
        int Pal = start_ge(32 + (st >> 1)); if (Pal > 1024) Pal = 1024;
        int v2  = 32 + ((st + 1) >> 1);
        int E2  = start_ge(v2); if (E2 > 1024) E2 = 1024;
        unsigned m = 0;
        for (int c = 0; c < 8; c++) {
            if (c * 128 + 128 > S)              m |= 1u << c;
            if (c < 4 && c * 128 < Pmu)         m |= 1u << (8 + c);
            if (c * 128 < Pal)                  m |= 1u << (12 + c);
            if (st < 63 && c * 128 < E2 && c * 128 + 128 > S)
                                                m |= 1u << (20 + c);
        }
        g_masks[st] = m;
    }
}

// --------- main: 4 warps = 4 rows; warp q owns chunks {q, q+4} ---------
__global__ void __launch_bounds__(NTHREADS, 4) maf_main(
    const float* __restrict__ z, const float* __restrict__ b2,
    float* __restrict__ out_x, float* __restrict__ out_ld)
{
    __shared__ __align__(16) float sw[3][3072];
    __shared__ __align__(16) float sred[2][8][4];  // [parity][class][quarter]
    __shared__ float zs[4][65];
    __shared__ float sx[4][65];                    // per-step x, written by warp 0
    __shared__ float b2s[128];
    __shared__ unsigned smq[4][64];                // per-warp pre-shifted masks

    const int tid = threadIdx.x;
    const int l   = tid & 31;
    const int q   = tid >> 5;                      // warp 0..3

    // stage z, b2 into smem
    for (int j = tid; j < 256; j += NTHREADS) {
        int r = j >> 6, c = j & 63;
        zs[r][c] = z[(blockIdx.x * 4 + r) * 64 + c];
    }
    b2s[tid] = b2[tid];
    // per-warp packed masks: bit0 W1 q, bit1 W1 q+4, bit2 mu q,
    //                        bit3 al q, bit4 al q+4, bit5 rf q, bit6 rf q+4
    for (int j = tid; j < 256; j += NTHREADS) {
        int w = j >> 6, st = j & 63;
        unsigned m = g_masks[st];
        unsigned mq = ((m >> w) & 1)
                    | (((m >> (w + 4)) & 1)  << 1)
                    | (((m >> (8 + w)) & 1)  << 2)
                    | (((m >> (12 + w)) & 1) << 3)
                    | (((m >> (16 + w)) & 1) << 4)
                    | (((m >> (20 + w)) & 1) << 5)
                    | (((m >> (24 + w)) & 1) << 6);
        smq[w][st] = mq;
    }

    // rotating stage base addresses + cp destinations
    unsigned swA = (unsigned)__cvta_generic_to_shared(&sw[0][0]);
    unsigned sw0 = swA, sw1 = swA + 12288, sw2 = swA + 24576;
    unsigned dst0 = sw0 + tid * 16, dst1 = sw1 + tid * 16, dst2 = sw2 + tid * 16;

    // prologue: prefetch steps 0 and 1 (unconditional full copies)
    {
        const float* s0 = g_w + tid * 4;
#pragma unroll
        for (int k = 0; k < 6; k++) cp16(dst0 + k * 2048, s0 + k * 512);
        cp_commit();
        const float* s1 = g_w + 3072 + tid * 4;
#pragma unroll
        for (int k = 0; k < 6; k++) cp16(dst1 + k * 2048, s1 + k * 512);
        cp_commit();
    }
    const float* srcp = g_w + 2 * 3072 + tid * 4;

    const unsigned laneoff = (unsigned)(q * 512 + l * 16);
    // hoisted per-lane invariants
    const bool isA = (l & 4);
    const float* b2p = b2s + (isA ? 64 : 0);
    const float* zp  = &zs[l & 3][0];
    const unsigned* smqp = &smq[q][0];

    // state: 4 rows x (chunk j: s[2j],s[2j+1], t likewise), chunk j -> q+4j
    ull sp[4][4], tp[4][4];
    const float4* b1v = (const float4*)(g_b1p);
#pragma unroll
    for (int j = 0; j < 2; j++) {
        float4 b = b1v[(q + 4 * j) * 32 + l];
        ull p01 = mk2(b.x, b.y), p23 = mk2(b.z, b.w);
        ull t01 = mk2(tanh_mufu(b.x), tanh_mufu(b.y));
        ull t23 = mk2(tanh_mufu(b.z), tanh_mufu(b.w));
#pragma unroll
        for (int r = 0; r < 4; r++) {
            sp[r][2*j] = p01; sp[r][2*j+1] = p23;
            tp[r][2*j] = t01; tp[r][2*j+1] = t23;
        }
    }

    float ld = 0.f;

    cp_wait1();          // stage 0 resident (warp-private cp.async)
    __syncthreads();     // publish z/b2/mask staging

#pragma unroll 2
    for (int i = 0; i < 64; i++) {
        const unsigned swb = sw0 + laneoff;
        const unsigned mq = smqp[i];

        // W1 chunks (held in regs across barrier); skip all-zero chunks
        ull w01[2], w23[2];
        if (mq & 1u) lds2(w01[0], w23[0], swb);
        if (mq & 2u) lds2(w01[1], w23[1], swb + 2048);

        // dots: 8 chains (4 rows x mu/alpha); mask-gated chunks
        ull acc[8];
#pragma unroll
        for (int c = 0; c < 8; c++) acc[c] = 0ull;
        if (mq & 4u) {                             // mu: only chunk j=0 can be live
            ull wm01, wm23;
            lds2(wm01, wm23, swb + 4096);
#pragma unroll
            for (int r = 0; r < 4; r++) {
                acc[r] = ffma2(tp[r][0], wm01, acc[r]);
                acc[r] = ffma2(tp[r][1], wm23, acc[r]);
            }
        }
        if (mq & 8u) {                             // alpha chunk j=0
            ull wa01, wa23;
            lds2(wa01, wa23, swb + 8192);
#pragma unroll
            for (int r = 0; r < 4; r++) {
                acc[4 + r] = ffma2(tp[r][0], wa01, acc[4 + r]);
                acc[4 + r] = ffma2(tp[r][1], wa23, acc[4 + r]);
            }
        }
        if (mq & 16u) {                            // alpha chunk j=1
            ull wa01, wa23;
            lds2(wa01, wa23, swb + 10240);
#pragma unroll
            for (int r = 0; r < 4; r++) {
                acc[4 + r] = ffma2(tp[r][2], wa01, acc[4 + r]);
                acc[4 + r] = ffma2(tp[r][3], wa23, acc[4 + r]);
            }
        }
        float v[8];
#pragma unroll
        for (int c = 0; c < 8; c++) { float u, w; un2(acc[c], u, w); v[c] = u + w; }

        // role-rotation reduction: 9 SHFL for 8 values; lane ends with class l&7
        float f;
        {
            bool b0 = l & 1;
            float s0_ = b0 ? v[0] : v[1], k0 = b0 ? v[1] : v[0];
            k0 += __shfl_xor_sync(0xffffffffu, s0_, 1);
            float s1_ = b0 ? v[2] : v[3], k1 = b0 ? v[3] : v[2];
            k1 += __shfl_xor_sync(0xffffffffu, s1_, 1);
            float s2_ = b0 ? v[4] : v[5], k2 = b0 ? v[5] : v[4];
            k2 += __shfl_xor_sync(0xffffffffu, s2_, 1);
            float s3_ = b0 ? v[6] : v[7], k3 = b0 ? v[7] : v[6];
            k3 += __shfl_xor_sync(0xffffffffu, s3_, 1);
            bool b1_ = l & 2;
            float sm = b1_ ? k0 : k1, km = b1_ ? k1 : k0;
            km += __shfl_xor_sync(0xffffffffu, sm, 2);
            float sa = b1_ ? k2 : k3, ka = b1_ ? k3 : k2;
            ka += __shfl_xor_sync(0xffffffffu, sa, 2);
            bool b2_ = l & 4;
            float sf = b2_ ? km : ka, kf = b2_ ? ka : km;
            kf += __shfl_xor_sync(0xffffffffu, sf, 4);
            kf += __shfl_xor_sync(0xffffffffu, kf, 8);
            kf += __shfl_xor_sync(0xffffffffu, kf, 16);
            f = kf;
        }
        if (l < 8) sred[i & 1][l][q] = f;

        // prefetch stage i+2: per-(section, warp) chunk predication
        {
            unsigned mq2 = (i + 2 < 64) ? smqp[i + 2] : 0u;
            if (mq2 & 1u)  cp16(dst2,         srcp);          // W1 chunk q
            if (mq2 & 2u)  cp16(dst2 + 2048,  srcp + 512);    // W1 chunk q+4
            if (mq2 & 4u)  cp16(dst2 + 4096,  srcp + 1024);   // mu chunk q
            // mu chunks 4-7 (section k=3) are never nonzero: never copied
            if (mq2 & 8u)  cp16(dst2 + 8192,  srcp + 2048);   // al chunk q
            if (mq2 & 16u) cp16(dst2 + 10240, srcp + 2560);   // al chunk q+4
            if (i + 2 < 64) srcp += 3072;
        }
        cp_commit();
        cp_wait1();          // stage i+1 resident (warp-private)
        __syncthreads();     // sred exchange

        // combine quarters for my class, add b2, exchange mu<->alpha
        float4 cf = *(const float4*)&sred[i & 1][l & 7][0];
        float cv = (cf.x + cf.y) + (cf.z + cf.w);
        cv += b2p[i];
        float pv = __shfl_xor_sync(0xffffffffu, cv, 4);
        float mu = isA ? pv : cv;
        float al = isA ? cv : pv;
        mu = fminf(fmaxf(mu, -CLAMPV), CLAMPV);
        al = fminf(fmaxf(al, -CLAMPV), CLAMPV);
        float x  = fmaf(zp[i], __expf(al), mu);
        ld += al;                                  // meaningful in alpha lanes

        if (q == 0 && l < 4) sx[l][i] = x;         // warp 0 records x

        float x0 = __shfl_sync(0xffffffffu, x, 0);
        float x1 = __shfl_sync(0xffffffffu, x, 1);
        float x2 = __shfl_sync(0xffffffffu, x, 2);
        float x3 = __shfl_sync(0xffffffffu, x, 3);

        // rank-1 update (register-held W1; mask-gated chunks)
        ull xx[4] = { mk2(x0, x0), mk2(x1, x1), mk2(x2, x2), mk2(x3, x3) };
        if (mq & 1u) {
#pragma unroll
            for (int r = 0; r < 4; r++) {
                sp[r][0] = ffma2(w01[0], xx[r], sp[r][0]);
                sp[r][1] = ffma2(w23[0], xx[r], sp[r][1]);
            }
        }
        if (mq & 2u) {
#pragma unroll
            for (int r = 0; r < 4; r++) {
                sp[r][2] = ffma2(w01[1], xx[r], sp[r][2]);
                sp[r][3] = ffma2(w23[1], xx[r], sp[r][3]);
            }
        }

        // lazy tanh refresh: mask-gated chunks (over-refresh safe)
        if (mq & 32u) {
#pragma unroll
            for (int r = 0; r < 4; r++) {
                float a0, a1_, c0, c1;
                un2(sp[r][0], a0, a1_);
                tp[r][0] = mk2(tanh_mufu(a0), tanh_mufu(a1_));
                un2(sp[r][1], c0, c1);
                tp[r][1] = mk2(tanh_mufu(c0), tanh_mufu(c1));
            }
        }
        if (mq & 64u) {
#pragma unroll
            for (int r = 0; r < 4; r++) {
                float a0, a1_, c0, c1;
                un2(sp[r][2], a0, a1_);
                tp[r][2] = mk2(tanh_mufu(a0), tanh_mufu(a1_));
                un2(sp[r][3], c0, c1);
                tp[r][3] = mk2(tanh_mufu(c0), tanh_mufu(c1));
            }
        }

        // rotate stage pointers + cp destinations (constant-folded under unroll 2)
        unsigned t = sw0; sw0 = sw1; sw1 = sw2; sw2 = t;
        unsigned td = dst0; dst0 = dst1; dst1 = dst2; dst2 = td;
    }

    // epilogue: warp 0 writes outputs from sx / ld classes
    if (q == 0) {
        __syncwarp();
        int base = blockIdx.x * 4;
#pragma unroll
        for (int r = 0; r < 4; r++) {
            float a = sx[r][2 * l], b = sx[r][2 * l + 1];
            if (!isfinite(a)) a = 0.f;
            if (!isfinite(b)) b = 0.f;
            *(float2*)(out_x + (base + r) * 64 + 2 * l) = make_float2(a, b);
        }
        if (l >= 4 && l < 8) {
            float L = ld;
            if (!isfinite(L)) L = 0.f;
            out_ld[base + (l - 4)] = L;
        }
    }
}

extern "C" void kernel_launch(void* const* d_in, const int* in_sizes, int n_in,
                              void* d_out, int out_size) {
    const float* z  = (const float*)d_in[0];   // (16384, 64)
    const float* W1 = (const float*)d_in[1];   // (1024, 64)
    const float* b1 = (const float*)d_in[2];   // (1024,)
    const float* W2 = (const float*)d_in[3];   // (128, 1024)
    const float* b2 = (const float*)d_in[4];   // (128,)
    float* out    = (float*)d_out;
    float* out_x  = out;                       // x: 16384*64 floats
    float* out_ld = out + B_ROWS * D_DIM;      // log_det: 16384 floats

    static int carveout_set = 0;
    if (!carveout_set) {
        cudaFuncSetAttribute(maf_main, cudaFuncAttributePreferredSharedMemoryCarveout, 100);
        carveout_set = 1;
    }

    maf_prep<<<768, 256>>>(W1, b1, W2);
    maf_main<<<B_ROWS / 4, NTHREADS>>>(z, b2, out_x, out_ld);  // 4 rows/block
}

// round 15
// speedup vs baseline: 1.0249x; 1.0249x over previous
#include <cuda_runtime.h>
#include <cuda_bf16.h>
#include <math.h>

// Shapes fixed by the problem: B=16384, D=64, H=1024, CLAMP=10.
#define B_ROWS 16384
#define D_DIM  64
#define H_DIM  1024
#define CLAMPV 10.0f
#define NTHREADS 128   // 4 warps = 4 rows per block; 4 blocks/SM

typedef unsigned long long ull;

// Packed weights, per step i (3072 floats each):
//   [0,1024)    : W1m column i   (masked, m0-sorted)
//   [1024,2048) : W2m row i      (mu row, masked)
//   [2048,3072) : W2m row 64+i   (alpha row, masked)
__device__ __align__(16) float g_w[64 * 3072];
__device__ __align__(16) float g_b1p[H_DIM];
// Per-step chunk-activity masks (8 chunks of 128 units):
//   bits [0:8)  W1 chunk nonzero   (c*128+128 > S_i)
//   bits [8:12) mu chunk nonzero   (c*128 < Pmu_i), c<4 (Pmu <= 512 always)
//   bits [12:20) alpha chunk nonzero (c*128 < Pal_i)
//   bits [20:28) tanh-refresh chunk  (overlaps [S_i, E2_i), i<63)
__device__ unsigned g_masks[64];

// m0[h] = h % 63 (values 0..62), H sorted stably by m0.
__host__ __device__ __forceinline__ int start_ge(int v) {
    return (v <= 16) ? 17 * v : 16 * v + 16;
}

__device__ __forceinline__ float tanh_mufu(float x) {
    float y; asm("tanh.approx.f32 %0, %1;" : "=f"(y) : "f"(x)); return y;
}
__device__ __forceinline__ ull ffma2(ull a, ull b, ull c) {
    ull d;
    asm("fma.rn.f32x2 %0, %1, %2, %3;" : "=l"(d) : "l"(a), "l"(b), "l"(c));
    return d;
}
__device__ __forceinline__ ull mk2(float lo, float hi) {
    ull r; asm("mov.b64 %0, {%1, %2};" : "=l"(r) : "f"(lo), "f"(hi)); return r;
}
__device__ __forceinline__ void un2(ull u, float& lo, float& hi) {
    asm("mov.b64 {%0, %1}, %2;" : "=f"(lo), "=f"(hi) : "l"(u));
}
__device__ __forceinline__ void lds2(ull& a, ull& b, unsigned addr) {
    asm volatile("ld.shared.v2.u64 {%0, %1}, [%2];" : "=l"(a), "=l"(b) : "r"(addr));
}
__device__ __forceinline__ void cp16(unsigned smem_dst, const void* gsrc) {
    asm volatile("cp.async.cg.shared.global [%0], [%1], 16;" :: "r"(smem_dst), "l"(gsrc));
}
__device__ __forceinline__ void cp_commit() {
    asm volatile("cp.async.commit_group;" ::: "memory");
}
__device__ __forceinline__ void cp_wait1() {
    asm volatile("cp.async.wait_group 1;" ::: "memory");
}

// ---------------- prep: permute + mask + pack weights + masks ----------------
__global__ void maf_prep(const float* __restrict__ W1,
                         const float* __restrict__ b1,
                         const float* __restrict__ W2) {
    int gid = blockIdx.x * blockDim.x + threadIdx.x;
    if (gid >= 64 * 3072) return;
    int i   = gid / 3072;
    int rem = gid - i * 3072;
    int sec = rem >> 10;
    int p   = rem & 1023;
    int v, k2;
    if (p < 272) { v = p / 17; k2 = p - v * 17; }
    else         { int r = p - 272; v = 16 + (r >> 4); k2 = r & 15; }
    int h = v + 63 * k2;

    float val;
    if (sec == 0)      val = (i <= v)            ? W1[h * 64 + i]          : 0.0f;
    else if (sec == 1) val = (v < (i >> 1))      ? W2[i * 1024 + h]        : 0.0f;
    else               val = (v < 32 + (i >> 1)) ? W2[(64 + i) * 1024 + h] : 0.0f;
    g_w[gid] = val;

    if (gid < 1024) {
        int pp = gid;
        int vv, kk;
        if (pp < 272) { vv = pp / 17; kk = pp - vv * 17; }
        else          { int r = pp - 272; vv = 16 + (r >> 4); kk = r & 15; }
        g_b1p[gid] = b1[vv + 63 * kk];
    }

    if (gid < 64) {
        int st = gid;
        int S   = start_ge(st);
        int Pmu = start_ge(st >> 1);
        int Pal = start_ge(32 + (st >> 1)); if (Pal > 1024) Pal = 1024;
        int v2  = 32 + ((st + 1) >> 1);
        int E2  = start_ge(v2); if (E2 > 1024) E2 = 1024;
        unsigned m = 0;
        for (int c = 0; c < 8; c++) {
            if (c * 128 + 128 > S)              m |= 1u << c;
            if (c < 4 && c * 128 < Pmu)         m |= 1u << (8 + c);
            if (c * 128 < Pal)                  m |= 1u << (12 + c);
            if (st < 63 && c * 128 < E2 && c * 128 + 128 > S)
                                                m |= 1u << (20 + c);
        }
        g_masks[st] = m;
    }
}

// --------- main: 4 warps = 4 rows; warp q owns chunks {q, q+4} ---------
// cp.async staging is warp-self-sufficient (thread copies exactly the bytes
// it reads), so weight visibility = program order + wait_group; the block
// barrier exists ONLY for the sred exchange and sits right after the STS.
__global__ void __launch_bounds__(NTHREADS, 4) maf_main(
    const float* __restrict__ z, const float* __restrict__ b2,
    float* __restrict__ out_x, float* __restrict__ out_ld)
{
    __shared__ __align__(16) float sw[3][3072];
    __shared__ __align__(16) float sred[2][8][4];  // [parity][class][quarter]
    __shared__ float zs[4][65];
    __shared__ float sx[4][65];                    // per-step x, written by warp 0
    __shared__ float b2s[128];
    __shared__ unsigned smq[4][64];                // per-warp pre-shifted masks

    const int tid = threadIdx.x;
    const int l   = tid & 31;
    const int q   = tid >> 5;                      // warp 0..3

    // stage z, b2 into smem
    for (int j = tid; j < 256; j += NTHREADS) {
        int r = j >> 6, c = j & 63;
        zs[r][c] = z[(blockIdx.x * 4 + r) * 64 + c];
    }
    b2s[tid] = b2[tid];
    // per-warp packed masks: bit0 W1 q, bit1 W1 q+4, bit2 mu q,
    //                        bit3 al q, bit4 al q+4, bit5 rf q, bit6 rf q+4
    for (int j = tid; j < 256; j += NTHREADS) {
        int w = j >> 6, st = j & 63;
        unsigned m = g_masks[st];
        unsigned mq = ((m >> w) & 1)
                    | (((m >> (w + 4)) & 1)  << 1)
                    | (((m >> (8 + w)) & 1)  << 2)
                    | (((m >> (12 + w)) & 1) << 3)
                    | (((m >> (16 + w)) & 1) << 4)
                    | (((m >> (20 + w)) & 1) << 5)
                    | (((m >> (24 + w)) & 1) << 6);
        smq[w][st] = mq;
    }

    // rotating stage base addresses + cp destinations
    unsigned swA = (unsigned)__cvta_generic_to_shared(&sw[0][0]);
    unsigned sw0 = swA, sw1 = swA + 12288, sw2 = swA + 24576;
    unsigned dst0 = sw0 + tid * 16, dst1 = sw1 + tid * 16, dst2 = sw2 + tid * 16;

    // prologue: prefetch steps 0 and 1 (unconditional full copies)
    {
        const float* s0 = g_w + tid * 4;
#pragma unroll
        for (int k = 0; k < 6; k++) cp16(dst0 + k * 2048, s0 + k * 512);
        cp_commit();
        const float* s1 = g_w + 3072 + tid * 4;
#pragma unroll
        for (int k = 0; k < 6; k++) cp16(dst1 + k * 2048, s1 + k * 512);
        cp_commit();
    }
    const float* srcp = g_w + 2 * 3072 + tid * 4;

    const unsigned laneoff = (unsigned)(q * 512 + l * 16);
    // hoisted per-lane invariants
    const bool isA = (l & 4);
    const float* b2p = b2s + (isA ? 64 : 0);
    const float* zp  = &zs[l & 3][0];
    const unsigned* smqp = &smq[q][0];

    // state: 4 rows x (chunk j: s[2j],s[2j+1], t likewise), chunk j -> q+4j
    ull sp[4][4], tp[4][4];
    const float4* b1v = (const float4*)(g_b1p);
#pragma unroll
    for (int j = 0; j < 2; j++) {
        float4 b = b1v[(q + 4 * j) * 32 + l];
        ull p01 = mk2(b.x, b.y), p23 = mk2(b.z, b.w);
        ull t01 = mk2(tanh_mufu(b.x), tanh_mufu(b.y));
        ull t23 = mk2(tanh_mufu(b.z), tanh_mufu(b.w));
#pragma unroll
        for (int r = 0; r < 4; r++) {
            sp[r][2*j] = p01; sp[r][2*j+1] = p23;
            tp[r][2*j] = t01; tp[r][2*j+1] = t23;
        }
    }

    float ld = 0.f;

    cp_wait1();          // stage 0 resident (warp-private cp.async)
    __syncthreads();     // publish z/b2/mask staging

#pragma unroll 1
    for (int i = 0; i < 64; i++) {
        const unsigned swb = sw0 + laneoff;
        const unsigned mq = smqp[i];

        // W1 chunks (held in regs); skip all-zero chunks
        ull w01[2], w23[2];
        if (mq & 1u) lds2(w01[0], w23[0], swb);
        if (mq & 2u) lds2(w01[1], w23[1], swb + 2048);

        // prefetch stage i+2 EARLY: the cp.async gets the whole step to land.
        // Buffer (i+2)%3 was last read at step i-1 by THIS thread; those LDS
        // results were consumed before this point -> same-thread ordering safe.
        {
            unsigned mq2 = (i + 2 < 64) ? smqp[i + 2] : 0u;
            if (mq2 & 1u)  cp16(dst2,         srcp);          // W1 chunk q
            if (mq2 & 2u)  cp16(dst2 + 2048,  srcp + 512);    // W1 chunk q+4
            if (mq2 & 4u)  cp16(dst2 + 4096,  srcp + 1024);   // mu chunk q
            // mu chunks 4-7 (section k=3) are never nonzero: never copied
            if (mq2 & 8u)  cp16(dst2 + 8192,  srcp + 2048);   // al chunk q
            if (mq2 & 16u) cp16(dst2 + 10240, srcp + 2560);   // al chunk q+4
            if (i + 2 < 64) srcp += 3072;
        }
        cp_commit();

        // dots: 8 chains (4 rows x mu/alpha); mask-gated chunks
        ull acc[8];
#pragma unroll
        for (int c = 0; c < 8; c++) acc[c] = 0ull;
        if (mq & 4u) {                             // mu: only chunk j=0 can be live
            ull wm01, wm23;
            lds2(wm01, wm23, swb + 4096);
#pragma unroll
            for (int r = 0; r < 4; r++) {
                acc[r] = ffma2(tp[r][0], wm01, acc[r]);
                acc[r] = ffma2(tp[r][1], wm23, acc[r]);
            }
        }
        if (mq & 8u) {                             // alpha chunk j=0
            ull wa01, wa23;
            lds2(wa01, wa23, swb + 8192);
#pragma unroll
            for (int r = 0; r < 4; r++) {
                acc[4 + r] = ffma2(tp[r][0], wa01, acc[4 + r]);
                acc[4 + r] = ffma2(tp[r][1], wa23, acc[4 + r]);
            }
        }
        if (mq & 16u) {                            // alpha chunk j=1
            ull wa01, wa23;
            lds2(wa01, wa23, swb + 10240);
#pragma unroll
            for (int r = 0; r < 4; r++) {
                acc[4 + r] = ffma2(tp[r][2], wa01, acc[4 + r]);
                acc[4 + r] = ffma2(tp[r][3], wa23, acc[4 + r]);
            }
        }
        float v[8];
#pragma unroll
        for (int c = 0; c < 8; c++) { float u, w; un2(acc[c], u, w); v[c] = u + w; }

        // role-rotation reduction: 9 SHFL for 8 values; lane ends with class l&7
        float f;
        {
            bool b0 = l & 1;
            float s0_ = b0 ? v[0] : v[1], k0 = b0 ? v[1] : v[0];
            k0 += __shfl_xor_sync(0xffffffffu, s0_, 1);
            float s1_ = b0 ? v[2] : v[3], k1 = b0 ? v[3] : v[2];
            k1 += __shfl_xor_sync(0xffffffffu, s1_, 1);
            float s2_ = b0 ? v[4] : v[5], k2 = b0 ? v[5] : v[4];
            k2 += __shfl_xor_sync(0xffffffffu, s2_, 1);
            float s3_ = b0 ? v[6] : v[7], k3 = b0 ? v[7] : v[6];
            k3 += __shfl_xor_sync(0xffffffffu, s3_, 1);
            bool b1_ = l & 2;
            float sm = b1_ ? k0 : k1, km = b1_ ? k1 : k0;
            km += __shfl_xor_sync(0xffffffffu, sm, 2);
            float sa = b1_ ? k2 : k3, ka = b1_ ? k3 : k2;
            ka += __shfl_xor_sync(0xffffffffu, sa, 2);
            bool b2_ = l & 4;
            float sf = b2_ ? km : ka, kf = b2_ ? ka : km;
            kf += __shfl_xor_sync(0xffffffffu, sf, 4);
            kf += __shfl_xor_sync(0xffffffffu, kf, 8);
            kf += __shfl_xor_sync(0xffffffffu, kf, 16);
            f = kf;
        }
        if (l < 8) sred[i & 1][l][q] = f;

        __syncthreads();     // sred exchange ONLY (weights are warp-private)

        // combine quarters for my class, add b2, exchange mu<->alpha
        float4 cf = *(const float4*)&sred[i & 1][l & 7][0];
        float cv = (cf.x + cf.y) + (cf.z + cf.w);
        cv += b2p[i];
        float pv = __shfl_xor_sync(0xffffffffu, cv, 4);
        float mu = isA ? pv : cv;
        float al = isA ? cv : pv;
        mu = fminf(fmaxf(mu, -CLAMPV), CLAMPV);
        al = fminf(fmaxf(al, -CLAMPV), CLAMPV);
        float x  = fmaf(zp[i], __expf(al), mu);
        ld += al;                                  // meaningful in alpha lanes

        if (q == 0 && l < 4) sx[l][i] = x;         // warp 0 records x

        float x0 = __shfl_sync(0xffffffffu, x, 0);
        float x1 = __shfl_sync(0xffffffffu, x, 1);
        float x2 = __shfl_sync(0xffffffffu, x, 2);
        float x3 = __shfl_sync(0xffffffffu, x, 3);

        // rank-1 update (register-held W1; mask-gated chunks)
        ull xx[4] = { mk2(x0, x0), mk2(x1, x1), mk2(x2, x2), mk2(x3, x3) };
        if (mq & 1u) {
#pragma unroll
            for (int r = 0; r < 4; r++) {
                sp[r][0] = ffma2(w01[0], xx[r], sp[r][0]);
                sp[r][1] = ffma2(w23[0], xx[r], sp[r][1]);
            }
        }
        if (mq & 2u) {
#pragma unroll
            for (int r = 0; r < 4; r++) {
                sp[r][2] = ffma2(w01[1], xx[r], sp[r][2]);
                sp[r][3] = ffma2(w23[1], xx[r], sp[r][3]);
            }
        }

        // lazy tanh refresh: mask-gated chunks (over-refresh safe)
        if (mq & 32u) {
#pragma unroll
            for (int r = 0; r < 4; r++) {
                float a0, a1_, c0, c1;
                un2(sp[r][0], a0, a1_);
                tp[r][0] = mk2(tanh_mufu(a0), tanh_mufu(a1_));
                un2(sp[r][1], c0, c1);
                tp[r][1] = mk2(tanh_mufu(c0), tanh_mufu(c1));
            }
        }
        if (mq & 64u) {
#pragma unroll
            for (int r = 0; r < 4; r++) {
                float a0, a1_, c0, c1;
                un2(sp[r][2], a0, a1_);
                tp[r][2] = mk2(tanh_mufu(a0), tanh_mufu(a1_));
                un2(sp[r][3], c0, c1);
                tp[r][3] = mk2(tanh_mufu(c0), tanh_mufu(c1));
            }
        }

        // stage i+1 must be resident before next iteration's lds2 (its group
        // was committed a full step ago -> this wait is nearly always free)
        cp_wait1();

        // rotate stage pointers + cp destinations
        unsigned t = sw0; sw0 = sw1; sw1 = sw2; sw2 = t;
        unsigned td = dst0; dst0 = dst1; dst1 = dst2; dst2 = td;
    }

    // epilogue: warp 0 writes outputs from sx / ld classes
    if (q == 0) {
        __syncwarp();
        int base = blockIdx.x * 4;
#pragma unroll
        for (int r = 0; r < 4; r++) {
            float a = sx[r][2 * l], b = sx[r][2 * l + 1];
            if (!isfinite(a)) a = 0.f;
            if (!isfinite(b)) b = 0.f;
            *(float2*)(out_x + (base + r) * 64 + 2 * l) = make_float2(a, b);
        }
        if (l >= 4 && l < 8) {
            float L = ld;
            if (!isfinite(L)) L = 0.f;
            out_ld[base + (l - 4)] = L;
        }
    }
}

extern "C" void kernel_launch(void* const* d_in, const int* in_sizes, int n_in,
                              void* d_out, int out_size) {
    const float* z  = (const float*)d_in[0];   // (16384, 64)
    const float* W1 = (const float*)d_in[1];   // (1024, 64)
    const float* b1 = (const float*)d_in[2];   // (1024,)
    const float* W2 = (const float*)d_in[3];   // (128, 1024)
    const float* b2 = (const float*)d_in[4];   // (128,)
    float* out    = (float*)d_out;
    float* out_x  = out;                       // x: 16384*64 floats
    float* out_ld = out + B_ROWS * D_DIM;      // log_det: 16384 floats

    static int carveout_set = 0;
    if (!carveout_set) {
        cudaFuncSetAttribute(maf_main, cudaFuncAttributePreferredSharedMemoryCarveout, 100);
        carveout_set = 1;
    }

    maf_prep<<<768, 256>>>(W1, b1, W2);
    maf_main<<<B_ROWS / 4, NTHREADS>>>(z, b2, out_x, out_ld);  // 4 rows/block
}